// round 4
// baseline (speedup 1.0000x reference)
#include <cuda_runtime.h>
#include <cuda_bf16.h>
#include <cstddef>

// Problem constants
#define Hh   512
#define INPS 2048
#define FS   1536
#define Bb   128
#define Tt   64
#define MROWS (Bb * Tt)          // 8192

// Persistent-recurrence tiling
#define NC   16                  // hidden cols per CTA
#define BBB  32                  // batch rows per CTA
#define NBLK 128                 // total CTAs (32 col-chunks x 4 batch-chunks)
#define STEP_THREADS 256

// Scratch for precomputed projections (device statics: allocation-free)
__device__ float g_gi[(size_t)MROWS * (3 * Hh)];   // [B*T, 1536]
__device__ float g_gf[(size_t)MROWS * (2 * Hh)];   // [B*T, 1024]
__device__ unsigned int g_bar;                      // grid-barrier counter (monotone)

// ---------------------------------------------------------------------------
// SGEMM: C[M,N] = A[M,K] * W[N,K]^T + bias[N]
// BM=BN=128, BK=16, TM=TN=8, 256 threads. All dims divisible by tiles here.
// ---------------------------------------------------------------------------
__global__ __launch_bounds__(256, 2)
void sgemm_bias_kernel(const float* __restrict__ A,
                       const float* __restrict__ W,
                       const float* __restrict__ bias,
                       float* __restrict__ C,
                       int M, int N, int K)
{
    constexpr int BM = 128, BN = 128, BK = 16, TM = 8, TN = 8;
    __shared__ float As[BK][BM];
    __shared__ float Ws[BK][BN];

    const int tid  = threadIdx.x;
    const int bm   = blockIdx.y;
    const int bn   = blockIdx.x;
    const int tcol = tid % (BN / TN);   // 0..15
    const int trow = tid / (BN / TN);   // 0..15

    const float* Ablk = A + (size_t)bm * BM * K;
    const float* Wblk = W + (size_t)bn * BN * K;

    float acc[TM][TN];
#pragma unroll
    for (int i = 0; i < TM; i++)
#pragma unroll
        for (int j = 0; j < TN; j++) acc[i][j] = 0.0f;

    for (int k0 = 0; k0 < K; k0 += BK) {
#pragma unroll
        for (int i = 0; i < 2; i++) {
            int idx = tid + i * 256;              // 0..511
            int row = idx >> 2;
            int kq  = idx & 3;
            float4 v = *(const float4*)(Ablk + (size_t)row * K + k0 + kq * 4);
            As[kq * 4 + 0][row] = v.x;
            As[kq * 4 + 1][row] = v.y;
            As[kq * 4 + 2][row] = v.z;
            As[kq * 4 + 3][row] = v.w;
        }
#pragma unroll
        for (int i = 0; i < 2; i++) {
            int idx = tid + i * 256;
            int row = idx >> 2;
            int kq  = idx & 3;
            float4 v = *(const float4*)(Wblk + (size_t)row * K + k0 + kq * 4);
            Ws[kq * 4 + 0][row] = v.x;
            Ws[kq * 4 + 1][row] = v.y;
            Ws[kq * 4 + 2][row] = v.z;
            Ws[kq * 4 + 3][row] = v.w;
        }
        __syncthreads();

#pragma unroll
        for (int k = 0; k < BK; k++) {
            float ra[TM], rb[TN];
            const float4* a4 = reinterpret_cast<const float4*>(&As[k][trow * TM]);
            const float4* b4 = reinterpret_cast<const float4*>(&Ws[k][tcol * TN]);
            float4 av0 = a4[0], av1 = a4[1];
            float4 bv0 = b4[0], bv1 = b4[1];
            ra[0]=av0.x; ra[1]=av0.y; ra[2]=av0.z; ra[3]=av0.w;
            ra[4]=av1.x; ra[5]=av1.y; ra[6]=av1.z; ra[7]=av1.w;
            rb[0]=bv0.x; rb[1]=bv0.y; rb[2]=bv0.z; rb[3]=bv0.w;
            rb[4]=bv1.x; rb[5]=bv1.y; rb[6]=bv1.z; rb[7]=bv1.w;
#pragma unroll
            for (int i = 0; i < TM; i++)
#pragma unroll
                for (int j = 0; j < TN; j++)
                    acc[i][j] = fmaf(ra[i], rb[j], acc[i][j]);
        }
        __syncthreads();
    }

    const int crow0 = bm * BM + trow * TM;
    const int ccol0 = bn * BN + tcol * TN;
#pragma unroll
    for (int i = 0; i < TM; i++) {
        float* crow = C + (size_t)(crow0 + i) * N + ccol0;
#pragma unroll
        for (int j = 0; j < TN; j++)
            crow[j] = acc[i][j] + bias[ccol0 + j];
    }
}

// ---------------------------------------------------------------------------
// Persistent GRU recurrence: ONE kernel runs all 64 timesteps.
// 128 CTAs (32 col-chunks x 4 batch-chunks), all co-resident (1/SM at 160KB smem).
// W_hh slice lives in smem for the whole kernel. Software grid barrier per step.
// Thread map: c = tid&15 (col within chunk), bg = tid>>4 (0..15) -> 2 batches.
// Register tile: 3 gates x 2 batches = 6 accumulators.
// ---------------------------------------------------------------------------
__global__ __launch_bounds__(STEP_THREADS, 1)
void gru_persistent_kernel(const float* __restrict__ gi,     // [B*T, 1536]
                           const float* __restrict__ gf,     // [B*T, 1024]
                           const float* __restrict__ W_hh,   // [1536, 512]
                           const float* __restrict__ b_hh,   // [1536]
                           float* __restrict__ out)          // eo [B,T,H] then hT [B,H]
{
    extern __shared__ float sm[];
    float* W_sm = sm;                        // [3][512][NC]  (k-major rows of NC cols)
    float* h_sm = sm + 3 * Hh * NC;          // [BBB][512]

    const int tid = threadIdx.x;
    const int c   = tid & (NC - 1);          // 0..15
    const int bg  = tid >> 4;                // 0..15
    const int colBase = blockIdx.x * NC;     // 0..496
    const int bBase   = blockIdx.y * BBB;    // 0..96
    const int n = colBase + c;

    // ---- One-time: stage W_hh slice (3 gates x NC cols x 512 k) into smem ----
    // Layout: W_sm[((g*512)+k)*NC + cc]  -> compute reads 16 consecutive floats.
    for (int i = tid; i < 3 * NC * (Hh / 4); i += STEP_THREADS) {
        int r  = i >> 7;          // row 0..(3*NC-1): g*NC + cc
        int kq = i & 127;         // float4 index over k
        int g  = r / NC;
        int cc = r - g * NC;
        float4 v = *(const float4*)(W_hh + (size_t)(g * Hh + colBase + cc) * Hh + kq * 4);
        int k = kq * 4;
        W_sm[((g * Hh) + k + 0) * NC + cc] = v.x;
        W_sm[((g * Hh) + k + 1) * NC + cc] = v.y;
        W_sm[((g * Hh) + k + 2) * NC + cc] = v.z;
        W_sm[((g * Hh) + k + 3) * NC + cc] = v.w;
    }

    const float bhr = b_hh[n];
    const float bhi = b_hh[Hh + n];
    const float bhn = b_hh[2 * Hh + n];

    for (int t = 0; t < Tt; t++) {
        // ---- Stage h_{t-1}[bBase..bBase+31, :] into smem ----
        if (t == 0) {
            float4 z = make_float4(0.f, 0.f, 0.f, 0.f);
            for (int i = tid; i < BBB * (Hh / 4); i += STEP_THREADS)
                *(float4*)(h_sm + i * 4) = z;
        } else {
            for (int i = tid; i < BBB * (Hh / 4); i += STEP_THREADS) {
                int bl = i >> 7;           // local batch
                int kq = i & 127;
                float4 v = *(const float4*)(out +
                    ((size_t)(bBase + bl) * Tt + (t - 1)) * Hh + kq * 4);
                *(float4*)(h_sm + bl * Hh + kq * 4) = v;
            }
        }
        __syncthreads();

        // ---- gh = h_{t-1} @ W_hh^T for this (batch,col) tile ----
        float a00 = 0.f, a01 = 0.f;   // gate r, batches j=0,1
        float a10 = 0.f, a11 = 0.f;   // gate i
        float a20 = 0.f, a21 = 0.f;   // gate n
        const float* h0p = h_sm + (bg * 2 + 0) * Hh;
        const float* h1p = h_sm + (bg * 2 + 1) * Hh;
        const float* w0p = W_sm + (0 * Hh) * NC + c;
        const float* w1p = W_sm + (1 * Hh) * NC + c;
        const float* w2p = W_sm + (2 * Hh) * NC + c;
#pragma unroll 8
        for (int k = 0; k < Hh; k++) {
            float h0 = h0p[k];
            float h1 = h1p[k];
            float w0 = w0p[k * NC];
            float w1 = w1p[k * NC];
            float w2 = w2p[k * NC];
            a00 = fmaf(w0, h0, a00);  a01 = fmaf(w0, h1, a01);
            a10 = fmaf(w1, h0, a10);  a11 = fmaf(w1, h1, a11);
            a20 = fmaf(w2, h0, a20);  a21 = fmaf(w2, h1, a21);
        }

        // ---- Gates + state update ----
#pragma unroll
        for (int j = 0; j < 2; j++) {
            const int b = bBase + bg * 2 + j;
            const size_t gib = ((size_t)b * Tt + t) * (3 * Hh);
            const size_t gfb = ((size_t)b * Tt + t) * (2 * Hh);

            float ghr = (j ? a01 : a00) + bhr;
            float ghi = (j ? a11 : a10) + bhi;
            float ghn = (j ? a21 : a20) + bhn;

            float xr = gi[gib + n]          + ghr + gf[gfb + n];
            float xi = gi[gib + Hh + n]     + ghi + gf[gfb + Hh + n];
            float resetgate = 1.0f / (1.0f + expf(-xr));
            float inputgate = 1.0f / (1.0f + expf(-xi));
            float newgate   = tanhf(gi[gib + 2 * Hh + n] + resetgate * ghn);

            float hprev = h_sm[(bg * 2 + j) * Hh + n];
            float hy = newgate + inputgate * (hprev - newgate);

            out[((size_t)b * Tt + t) * Hh + n] = hy;
            if (t == Tt - 1)
                out[(size_t)Bb * Tt * Hh + (size_t)b * Hh + n] = hy;
        }

        // ---- Grid-wide barrier (all 128 CTAs co-resident) ----
        __threadfence();          // make this step's out[] writes visible GPU-wide
        __syncthreads();          // all threads of CTA done (writes + h_sm reads)
        if (tid == 0) {
            unsigned int old  = atomicAdd(&g_bar, 1u);
            unsigned int need = (old / NBLK + 1u) * NBLK;
            while (true) {
                unsigned int cur;
                asm volatile("ld.acquire.gpu.u32 %0, [%1];"
                             : "=r"(cur) : "l"(&g_bar));
                if (cur >= need) break;
            }
            __threadfence();
        }
        __syncthreads();
    }
}

// ---------------------------------------------------------------------------
// Launch
// ---------------------------------------------------------------------------
extern "C" void kernel_launch(void* const* d_in, const int* in_sizes, int n_in,
                              void* d_out, int out_size)
{
    const float* feat0 = (const float*)d_in[0];   // [B,T,FS]
    const float* feat1 = (const float*)d_in[1];   // [B,T,IN]
    const float* W_ih  = (const float*)d_in[2];   // [3H, IN]
    const float* b_ih  = (const float*)d_in[3];   // [3H]
    const float* W_hh  = (const float*)d_in[4];   // [3H, H]
    const float* b_hh  = (const float*)d_in[5];   // [3H]
    const float* W_fh  = (const float*)d_in[6];   // [2H, FS]
    const float* b_fh  = (const float*)d_in[7];   // [2H]
    float* out = (float*)d_out;

    float *gi_ptr, *gf_ptr;
    cudaGetSymbolAddress((void**)&gi_ptr, g_gi);
    cudaGetSymbolAddress((void**)&gf_ptr, g_gf);

    // gi = feat1 @ W_ih^T + b_ih : M=8192, N=1536, K=2048
    {
        dim3 grid((3 * Hh) / 128, MROWS / 128);
        sgemm_bias_kernel<<<grid, 256>>>(feat1, W_ih, b_ih, gi_ptr,
                                         MROWS, 3 * Hh, INPS);
    }
    // gf = feat0 @ W_fh^T + b_fh : M=8192, N=1024, K=1536
    {
        dim3 grid((2 * Hh) / 128, MROWS / 128);
        sgemm_bias_kernel<<<grid, 256>>>(feat0, W_fh, b_fh, gf_ptr,
                                         MROWS, 2 * Hh, FS);
    }
    // Recurrence: single persistent kernel, 64 steps internally
    {
        const int smem_bytes = (3 * Hh * NC + BBB * Hh) * (int)sizeof(float); // 163840
        cudaFuncSetAttribute(gru_persistent_kernel,
                             cudaFuncAttributeMaxDynamicSharedMemorySize, smem_bytes);
        dim3 grid(Hh / NC, Bb / BBB);   // (32, 4) = 128 CTAs
        gru_persistent_kernel<<<grid, STEP_THREADS, smem_bytes>>>(
            gi_ptr, gf_ptr, W_hh, b_hh, out);
    }
}

// round 5
// speedup vs baseline: 1.0020x; 1.0020x over previous
#include <cuda_runtime.h>
#include <cuda_bf16.h>
#include <cstddef>

// Problem constants
#define Hh   512
#define INPS 2048
#define FS   1536
#define Bb   128
#define Tt   64
#define MROWS (Bb * Tt)          // 8192

// Persistent-recurrence tiling
#define NC   16                  // hidden cols per CTA
#define BBB  32                  // batch rows per CTA
#define NBLK 128                 // total CTAs (32 col-chunks x 4 batch-chunks)
#define STEP_THREADS 256

// Scratch for precomputed projections (device statics: allocation-free)
__device__ float g_gi[(size_t)MROWS * (3 * Hh)];   // [B*T, 1536]
__device__ float g_gf[(size_t)MROWS * (2 * Hh)];   // [B*T, 1024]
__device__ unsigned int g_bar;                      // grid-barrier counter (monotone)

// ---------------------------------------------------------------------------
// SGEMM: C[M,N] = A[M,K] * W[N,K]^T + bias[N]
// BM=BN=128, BK=16, TM=TN=8, 256 threads. All dims divisible by tiles here.
// ---------------------------------------------------------------------------
__global__ __launch_bounds__(256, 2)
void sgemm_bias_kernel(const float* __restrict__ A,
                       const float* __restrict__ W,
                       const float* __restrict__ bias,
                       float* __restrict__ C,
                       int M, int N, int K)
{
    constexpr int BM = 128, BN = 128, BK = 16, TM = 8, TN = 8;
    __shared__ float As[BK][BM];
    __shared__ float Ws[BK][BN];

    const int tid  = threadIdx.x;
    const int bm   = blockIdx.y;
    const int bn   = blockIdx.x;
    const int tcol = tid % (BN / TN);   // 0..15
    const int trow = tid / (BN / TN);   // 0..15

    const float* Ablk = A + (size_t)bm * BM * K;
    const float* Wblk = W + (size_t)bn * BN * K;

    float acc[TM][TN];
#pragma unroll
    for (int i = 0; i < TM; i++)
#pragma unroll
        for (int j = 0; j < TN; j++) acc[i][j] = 0.0f;

    for (int k0 = 0; k0 < K; k0 += BK) {
#pragma unroll
        for (int i = 0; i < 2; i++) {
            int idx = tid + i * 256;              // 0..511
            int row = idx >> 2;
            int kq  = idx & 3;
            float4 v = *(const float4*)(Ablk + (size_t)row * K + k0 + kq * 4);
            As[kq * 4 + 0][row] = v.x;
            As[kq * 4 + 1][row] = v.y;
            As[kq * 4 + 2][row] = v.z;
            As[kq * 4 + 3][row] = v.w;
        }
#pragma unroll
        for (int i = 0; i < 2; i++) {
            int idx = tid + i * 256;
            int row = idx >> 2;
            int kq  = idx & 3;
            float4 v = *(const float4*)(Wblk + (size_t)row * K + k0 + kq * 4);
            Ws[kq * 4 + 0][row] = v.x;
            Ws[kq * 4 + 1][row] = v.y;
            Ws[kq * 4 + 2][row] = v.z;
            Ws[kq * 4 + 3][row] = v.w;
        }
        __syncthreads();

#pragma unroll
        for (int k = 0; k < BK; k++) {
            float ra[TM], rb[TN];
            const float4* a4 = reinterpret_cast<const float4*>(&As[k][trow * TM]);
            const float4* b4 = reinterpret_cast<const float4*>(&Ws[k][tcol * TN]);
            float4 av0 = a4[0], av1 = a4[1];
            float4 bv0 = b4[0], bv1 = b4[1];
            ra[0]=av0.x; ra[1]=av0.y; ra[2]=av0.z; ra[3]=av0.w;
            ra[4]=av1.x; ra[5]=av1.y; ra[6]=av1.z; ra[7]=av1.w;
            rb[0]=bv0.x; rb[1]=bv0.y; rb[2]=bv0.z; rb[3]=bv0.w;
            rb[4]=bv1.x; rb[5]=bv1.y; rb[6]=bv1.z; rb[7]=bv1.w;
#pragma unroll
            for (int i = 0; i < TM; i++)
#pragma unroll
                for (int j = 0; j < TN; j++)
                    acc[i][j] = fmaf(ra[i], rb[j], acc[i][j]);
        }
        __syncthreads();
    }

    const int crow0 = bm * BM + trow * TM;
    const int ccol0 = bn * BN + tcol * TN;
#pragma unroll
    for (int i = 0; i < TM; i++) {
        float* crow = C + (size_t)(crow0 + i) * N + ccol0;
#pragma unroll
        for (int j = 0; j < TN; j++)
            crow[j] = acc[i][j] + bias[ccol0 + j];
    }
}

// ---------------------------------------------------------------------------
// Persistent GRU recurrence: ONE kernel runs all 64 timesteps.
// 128 CTAs (32 col-chunks x 4 batch-chunks), all co-resident (1/SM at 160KB smem).
// W_hh slice lives in smem for the whole kernel. Software grid barrier per step.
// Thread map: c = tid&15 (col within chunk), bg = tid>>4 (0..15) -> 2 batches.
// Register tile: 3 gates x 2 batches = 6 accumulators.
// ---------------------------------------------------------------------------
__global__ __launch_bounds__(STEP_THREADS, 1)
void gru_persistent_kernel(const float* __restrict__ gi,     // [B*T, 1536]
                           const float* __restrict__ gf,     // [B*T, 1024]
                           const float* __restrict__ W_hh,   // [1536, 512]
                           const float* __restrict__ b_hh,   // [1536]
                           float* __restrict__ out)          // eo [B,T,H] then hT [B,H]
{
    extern __shared__ float sm[];
    float* W_sm = sm;                        // [3][512][NC]  (k-major rows of NC cols)
    float* h_sm = sm + 3 * Hh * NC;          // [BBB][512]

    const int tid = threadIdx.x;
    const int c   = tid & (NC - 1);          // 0..15
    const int bg  = tid >> 4;                // 0..15
    const int colBase = blockIdx.x * NC;     // 0..496
    const int bBase   = blockIdx.y * BBB;    // 0..96
    const int n = colBase + c;

    // ---- One-time: stage W_hh slice (3 gates x NC cols x 512 k) into smem ----
    // Layout: W_sm[((g*512)+k)*NC + cc]  -> compute reads 16 consecutive floats.
    for (int i = tid; i < 3 * NC * (Hh / 4); i += STEP_THREADS) {
        int r  = i >> 7;          // row 0..(3*NC-1): g*NC + cc
        int kq = i & 127;         // float4 index over k
        int g  = r / NC;
        int cc = r - g * NC;
        float4 v = *(const float4*)(W_hh + (size_t)(g * Hh + colBase + cc) * Hh + kq * 4);
        int k = kq * 4;
        W_sm[((g * Hh) + k + 0) * NC + cc] = v.x;
        W_sm[((g * Hh) + k + 1) * NC + cc] = v.y;
        W_sm[((g * Hh) + k + 2) * NC + cc] = v.z;
        W_sm[((g * Hh) + k + 3) * NC + cc] = v.w;
    }

    const float bhr = b_hh[n];
    const float bhi = b_hh[Hh + n];
    const float bhn = b_hh[2 * Hh + n];

    for (int t = 0; t < Tt; t++) {
        // ---- Stage h_{t-1}[bBase..bBase+31, :] into smem ----
        if (t == 0) {
            float4 z = make_float4(0.f, 0.f, 0.f, 0.f);
            for (int i = tid; i < BBB * (Hh / 4); i += STEP_THREADS)
                *(float4*)(h_sm + i * 4) = z;
        } else {
            for (int i = tid; i < BBB * (Hh / 4); i += STEP_THREADS) {
                int bl = i >> 7;           // local batch
                int kq = i & 127;
                float4 v = *(const float4*)(out +
                    ((size_t)(bBase + bl) * Tt + (t - 1)) * Hh + kq * 4);
                *(float4*)(h_sm + bl * Hh + kq * 4) = v;
            }
        }
        __syncthreads();

        // ---- gh = h_{t-1} @ W_hh^T for this (batch,col) tile ----
        float a00 = 0.f, a01 = 0.f;   // gate r, batches j=0,1
        float a10 = 0.f, a11 = 0.f;   // gate i
        float a20 = 0.f, a21 = 0.f;   // gate n
        const float* h0p = h_sm + (bg * 2 + 0) * Hh;
        const float* h1p = h_sm + (bg * 2 + 1) * Hh;
        const float* w0p = W_sm + (0 * Hh) * NC + c;
        const float* w1p = W_sm + (1 * Hh) * NC + c;
        const float* w2p = W_sm + (2 * Hh) * NC + c;
#pragma unroll 8
        for (int k = 0; k < Hh; k++) {
            float h0 = h0p[k];
            float h1 = h1p[k];
            float w0 = w0p[k * NC];
            float w1 = w1p[k * NC];
            float w2 = w2p[k * NC];
            a00 = fmaf(w0, h0, a00);  a01 = fmaf(w0, h1, a01);
            a10 = fmaf(w1, h0, a10);  a11 = fmaf(w1, h1, a11);
            a20 = fmaf(w2, h0, a20);  a21 = fmaf(w2, h1, a21);
        }

        // ---- Gates + state update ----
#pragma unroll
        for (int j = 0; j < 2; j++) {
            const int b = bBase + bg * 2 + j;
            const size_t gib = ((size_t)b * Tt + t) * (3 * Hh);
            const size_t gfb = ((size_t)b * Tt + t) * (2 * Hh);

            float ghr = (j ? a01 : a00) + bhr;
            float ghi = (j ? a11 : a10) + bhi;
            float ghn = (j ? a21 : a20) + bhn;

            float xr = gi[gib + n]          + ghr + gf[gfb + n];
            float xi = gi[gib + Hh + n]     + ghi + gf[gfb + Hh + n];
            float resetgate = 1.0f / (1.0f + expf(-xr));
            float inputgate = 1.0f / (1.0f + expf(-xi));
            float newgate   = tanhf(gi[gib + 2 * Hh + n] + resetgate * ghn);

            float hprev = h_sm[(bg * 2 + j) * Hh + n];
            float hy = newgate + inputgate * (hprev - newgate);

            out[((size_t)b * Tt + t) * Hh + n] = hy;
            if (t == Tt - 1)
                out[(size_t)Bb * Tt * Hh + (size_t)b * Hh + n] = hy;
        }

        // ---- Grid-wide barrier (all 128 CTAs co-resident) ----
        __threadfence();          // make this step's out[] writes visible GPU-wide
        __syncthreads();          // all threads of CTA done (writes + h_sm reads)
        if (tid == 0) {
            unsigned int old  = atomicAdd(&g_bar, 1u);
            unsigned int need = (old / NBLK + 1u) * NBLK;
            while (true) {
                unsigned int cur;
                asm volatile("ld.acquire.gpu.u32 %0, [%1];"
                             : "=r"(cur) : "l"(&g_bar));
                if (cur >= need) break;
            }
            __threadfence();
        }
        __syncthreads();
    }
}

// ---------------------------------------------------------------------------
// Launch
// ---------------------------------------------------------------------------
extern "C" void kernel_launch(void* const* d_in, const int* in_sizes, int n_in,
                              void* d_out, int out_size)
{
    const float* feat0 = (const float*)d_in[0];   // [B,T,FS]
    const float* feat1 = (const float*)d_in[1];   // [B,T,IN]
    const float* W_ih  = (const float*)d_in[2];   // [3H, IN]
    const float* b_ih  = (const float*)d_in[3];   // [3H]
    const float* W_hh  = (const float*)d_in[4];   // [3H, H]
    const float* b_hh  = (const float*)d_in[5];   // [3H]
    const float* W_fh  = (const float*)d_in[6];   // [2H, FS]
    const float* b_fh  = (const float*)d_in[7];   // [2H]
    float* out = (float*)d_out;

    float *gi_ptr, *gf_ptr;
    cudaGetSymbolAddress((void**)&gi_ptr, g_gi);
    cudaGetSymbolAddress((void**)&gf_ptr, g_gf);

    // gi = feat1 @ W_ih^T + b_ih : M=8192, N=1536, K=2048
    {
        dim3 grid((3 * Hh) / 128, MROWS / 128);
        sgemm_bias_kernel<<<grid, 256>>>(feat1, W_ih, b_ih, gi_ptr,
                                         MROWS, 3 * Hh, INPS);
    }
    // gf = feat0 @ W_fh^T + b_fh : M=8192, N=1024, K=1536
    {
        dim3 grid((2 * Hh) / 128, MROWS / 128);
        sgemm_bias_kernel<<<grid, 256>>>(feat0, W_fh, b_fh, gf_ptr,
                                         MROWS, 2 * Hh, FS);
    }
    // Recurrence: single persistent kernel, 64 steps internally
    {
        const int smem_bytes = (3 * Hh * NC + BBB * Hh) * (int)sizeof(float); // 163840
        cudaFuncSetAttribute(gru_persistent_kernel,
                             cudaFuncAttributeMaxDynamicSharedMemorySize, smem_bytes);
        dim3 grid(Hh / NC, Bb / BBB);   // (32, 4) = 128 CTAs
        gru_persistent_kernel<<<grid, STEP_THREADS, smem_bytes>>>(
            gi_ptr, gf_ptr, W_hh, b_hh, out);
    }
}

// round 6
// speedup vs baseline: 1.0025x; 1.0005x over previous
#include <cuda_runtime.h>
#include <cuda_bf16.h>
#include <cstddef>

// Problem constants
#define Hh   512
#define INPS 2048
#define FS   1536
#define Bb   128
#define Tt   64
#define MROWS (Bb * Tt)          // 8192

// Persistent-recurrence tiling
#define NC   16                  // hidden cols per CTA
#define BBB  32                  // batch rows per CTA
#define NBLK 128                 // total CTAs (32 col-chunks x 4 batch-chunks)
#define STEP_THREADS 256

// Scratch for precomputed projections (device statics: allocation-free)
__device__ float g_gi[(size_t)MROWS * (3 * Hh)];   // [B*T, 1536]
__device__ float g_gf[(size_t)MROWS * (2 * Hh)];   // [B*T, 1024]
__device__ unsigned int g_bar;                      // grid-barrier counter (monotone)

// ---------------------------------------------------------------------------
// SGEMM: C[M,N] = A[M,K] * W[N,K]^T + bias[N]
// BM=BN=128, BK=16, TM=TN=8, 256 threads. All dims divisible by tiles here.
// ---------------------------------------------------------------------------
__global__ __launch_bounds__(256, 2)
void sgemm_bias_kernel(const float* __restrict__ A,
                       const float* __restrict__ W,
                       const float* __restrict__ bias,
                       float* __restrict__ C,
                       int M, int N, int K)
{
    constexpr int BM = 128, BN = 128, BK = 16, TM = 8, TN = 8;
    __shared__ float As[BK][BM];
    __shared__ float Ws[BK][BN];

    const int tid  = threadIdx.x;
    const int bm   = blockIdx.y;
    const int bn   = blockIdx.x;
    const int tcol = tid % (BN / TN);   // 0..15
    const int trow = tid / (BN / TN);   // 0..15

    const float* Ablk = A + (size_t)bm * BM * K;
    const float* Wblk = W + (size_t)bn * BN * K;

    float acc[TM][TN];
#pragma unroll
    for (int i = 0; i < TM; i++)
#pragma unroll
        for (int j = 0; j < TN; j++) acc[i][j] = 0.0f;

    for (int k0 = 0; k0 < K; k0 += BK) {
#pragma unroll
        for (int i = 0; i < 2; i++) {
            int idx = tid + i * 256;              // 0..511
            int row = idx >> 2;
            int kq  = idx & 3;
            float4 v = *(const float4*)(Ablk + (size_t)row * K + k0 + kq * 4);
            As[kq * 4 + 0][row] = v.x;
            As[kq * 4 + 1][row] = v.y;
            As[kq * 4 + 2][row] = v.z;
            As[kq * 4 + 3][row] = v.w;
        }
#pragma unroll
        for (int i = 0; i < 2; i++) {
            int idx = tid + i * 256;
            int row = idx >> 2;
            int kq  = idx & 3;
            float4 v = *(const float4*)(Wblk + (size_t)row * K + k0 + kq * 4);
            Ws[kq * 4 + 0][row] = v.x;
            Ws[kq * 4 + 1][row] = v.y;
            Ws[kq * 4 + 2][row] = v.z;
            Ws[kq * 4 + 3][row] = v.w;
        }
        __syncthreads();

#pragma unroll
        for (int k = 0; k < BK; k++) {
            float ra[TM], rb[TN];
            const float4* a4 = reinterpret_cast<const float4*>(&As[k][trow * TM]);
            const float4* b4 = reinterpret_cast<const float4*>(&Ws[k][tcol * TN]);
            float4 av0 = a4[0], av1 = a4[1];
            float4 bv0 = b4[0], bv1 = b4[1];
            ra[0]=av0.x; ra[1]=av0.y; ra[2]=av0.z; ra[3]=av0.w;
            ra[4]=av1.x; ra[5]=av1.y; ra[6]=av1.z; ra[7]=av1.w;
            rb[0]=bv0.x; rb[1]=bv0.y; rb[2]=bv0.z; rb[3]=bv0.w;
            rb[4]=bv1.x; rb[5]=bv1.y; rb[6]=bv1.z; rb[7]=bv1.w;
#pragma unroll
            for (int i = 0; i < TM; i++)
#pragma unroll
                for (int j = 0; j < TN; j++)
                    acc[i][j] = fmaf(ra[i], rb[j], acc[i][j]);
        }
        __syncthreads();
    }

    const int crow0 = bm * BM + trow * TM;
    const int ccol0 = bn * BN + tcol * TN;
#pragma unroll
    for (int i = 0; i < TM; i++) {
        float* crow = C + (size_t)(crow0 + i) * N + ccol0;
#pragma unroll
        for (int j = 0; j < TN; j++)
            crow[j] = acc[i][j] + bias[ccol0 + j];
    }
}

// ---------------------------------------------------------------------------
// Persistent GRU recurrence: ONE kernel runs all 64 timesteps.
// 128 CTAs (32 col-chunks x 4 batch-chunks), all co-resident (1/SM at 160KB smem).
// W_hh slice lives in smem for the whole kernel. Software grid barrier per step.
// Thread map: c = tid&15 (col within chunk), bg = tid>>4 (0..15) -> 2 batches.
// Register tile: 3 gates x 2 batches = 6 accumulators.
// ---------------------------------------------------------------------------
__global__ __launch_bounds__(STEP_THREADS, 1)
void gru_persistent_kernel(const float* __restrict__ gi,     // [B*T, 1536]
                           const float* __restrict__ gf,     // [B*T, 1024]
                           const float* __restrict__ W_hh,   // [1536, 512]
                           const float* __restrict__ b_hh,   // [1536]
                           float* __restrict__ out)          // eo [B,T,H] then hT [B,H]
{
    extern __shared__ float sm[];
    float* W_sm = sm;                        // [3][512][NC]  (k-major rows of NC cols)
    float* h_sm = sm + 3 * Hh * NC;          // [BBB][512]

    const int tid = threadIdx.x;
    const int c   = tid & (NC - 1);          // 0..15
    const int bg  = tid >> 4;                // 0..15
    const int colBase = blockIdx.x * NC;     // 0..496
    const int bBase   = blockIdx.y * BBB;    // 0..96
    const int n = colBase + c;

    // ---- One-time: stage W_hh slice (3 gates x NC cols x 512 k) into smem ----
    // Layout: W_sm[((g*512)+k)*NC + cc]  -> compute reads 16 consecutive floats.
    for (int i = tid; i < 3 * NC * (Hh / 4); i += STEP_THREADS) {
        int r  = i >> 7;          // row 0..(3*NC-1): g*NC + cc
        int kq = i & 127;         // float4 index over k
        int g  = r / NC;
        int cc = r - g * NC;
        float4 v = *(const float4*)(W_hh + (size_t)(g * Hh + colBase + cc) * Hh + kq * 4);
        int k = kq * 4;
        W_sm[((g * Hh) + k + 0) * NC + cc] = v.x;
        W_sm[((g * Hh) + k + 1) * NC + cc] = v.y;
        W_sm[((g * Hh) + k + 2) * NC + cc] = v.z;
        W_sm[((g * Hh) + k + 3) * NC + cc] = v.w;
    }

    const float bhr = b_hh[n];
    const float bhi = b_hh[Hh + n];
    const float bhn = b_hh[2 * Hh + n];

    for (int t = 0; t < Tt; t++) {
        // ---- Stage h_{t-1}[bBase..bBase+31, :] into smem ----
        if (t == 0) {
            float4 z = make_float4(0.f, 0.f, 0.f, 0.f);
            for (int i = tid; i < BBB * (Hh / 4); i += STEP_THREADS)
                *(float4*)(h_sm + i * 4) = z;
        } else {
            for (int i = tid; i < BBB * (Hh / 4); i += STEP_THREADS) {
                int bl = i >> 7;           // local batch
                int kq = i & 127;
                float4 v = *(const float4*)(out +
                    ((size_t)(bBase + bl) * Tt + (t - 1)) * Hh + kq * 4);
                *(float4*)(h_sm + bl * Hh + kq * 4) = v;
            }
        }
        __syncthreads();

        // ---- gh = h_{t-1} @ W_hh^T for this (batch,col) tile ----
        float a00 = 0.f, a01 = 0.f;   // gate r, batches j=0,1
        float a10 = 0.f, a11 = 0.f;   // gate i
        float a20 = 0.f, a21 = 0.f;   // gate n
        const float* h0p = h_sm + (bg * 2 + 0) * Hh;
        const float* h1p = h_sm + (bg * 2 + 1) * Hh;
        const float* w0p = W_sm + (0 * Hh) * NC + c;
        const float* w1p = W_sm + (1 * Hh) * NC + c;
        const float* w2p = W_sm + (2 * Hh) * NC + c;
#pragma unroll 8
        for (int k = 0; k < Hh; k++) {
            float h0 = h0p[k];
            float h1 = h1p[k];
            float w0 = w0p[k * NC];
            float w1 = w1p[k * NC];
            float w2 = w2p[k * NC];
            a00 = fmaf(w0, h0, a00);  a01 = fmaf(w0, h1, a01);
            a10 = fmaf(w1, h0, a10);  a11 = fmaf(w1, h1, a11);
            a20 = fmaf(w2, h0, a20);  a21 = fmaf(w2, h1, a21);
        }

        // ---- Gates + state update ----
#pragma unroll
        for (int j = 0; j < 2; j++) {
            const int b = bBase + bg * 2 + j;
            const size_t gib = ((size_t)b * Tt + t) * (3 * Hh);
            const size_t gfb = ((size_t)b * Tt + t) * (2 * Hh);

            float ghr = (j ? a01 : a00) + bhr;
            float ghi = (j ? a11 : a10) + bhi;
            float ghn = (j ? a21 : a20) + bhn;

            float xr = gi[gib + n]          + ghr + gf[gfb + n];
            float xi = gi[gib + Hh + n]     + ghi + gf[gfb + Hh + n];
            float resetgate = 1.0f / (1.0f + expf(-xr));
            float inputgate = 1.0f / (1.0f + expf(-xi));
            float newgate   = tanhf(gi[gib + 2 * Hh + n] + resetgate * ghn);

            float hprev = h_sm[(bg * 2 + j) * Hh + n];
            float hy = newgate + inputgate * (hprev - newgate);

            out[((size_t)b * Tt + t) * Hh + n] = hy;
            if (t == Tt - 1)
                out[(size_t)Bb * Tt * Hh + (size_t)b * Hh + n] = hy;
        }

        // ---- Grid-wide barrier (all 128 CTAs co-resident) ----
        __threadfence();          // make this step's out[] writes visible GPU-wide
        __syncthreads();          // all threads of CTA done (writes + h_sm reads)
        if (tid == 0) {
            unsigned int old  = atomicAdd(&g_bar, 1u);
            unsigned int need = (old / NBLK + 1u) * NBLK;
            while (true) {
                unsigned int cur;
                asm volatile("ld.acquire.gpu.u32 %0, [%1];"
                             : "=r"(cur) : "l"(&g_bar));
                if (cur >= need) break;
            }
            __threadfence();
        }
        __syncthreads();
    }
}

// ---------------------------------------------------------------------------
// Launch
// ---------------------------------------------------------------------------
extern "C" void kernel_launch(void* const* d_in, const int* in_sizes, int n_in,
                              void* d_out, int out_size)
{
    const float* feat0 = (const float*)d_in[0];   // [B,T,FS]
    const float* feat1 = (const float*)d_in[1];   // [B,T,IN]
    const float* W_ih  = (const float*)d_in[2];   // [3H, IN]
    const float* b_ih  = (const float*)d_in[3];   // [3H]
    const float* W_hh  = (const float*)d_in[4];   // [3H, H]
    const float* b_hh  = (const float*)d_in[5];   // [3H]
    const float* W_fh  = (const float*)d_in[6];   // [2H, FS]
    const float* b_fh  = (const float*)d_in[7];   // [2H]
    float* out = (float*)d_out;

    float *gi_ptr, *gf_ptr;
    cudaGetSymbolAddress((void**)&gi_ptr, g_gi);
    cudaGetSymbolAddress((void**)&gf_ptr, g_gf);

    // gi = feat1 @ W_ih^T + b_ih : M=8192, N=1536, K=2048
    {
        dim3 grid((3 * Hh) / 128, MROWS / 128);
        sgemm_bias_kernel<<<grid, 256>>>(feat1, W_ih, b_ih, gi_ptr,
                                         MROWS, 3 * Hh, INPS);
    }
    // gf = feat0 @ W_fh^T + b_fh : M=8192, N=1024, K=1536
    {
        dim3 grid((2 * Hh) / 128, MROWS / 128);
        sgemm_bias_kernel<<<grid, 256>>>(feat0, W_fh, b_fh, gf_ptr,
                                         MROWS, 2 * Hh, FS);
    }
    // Recurrence: single persistent kernel, 64 steps internally
    {
        const int smem_bytes = (3 * Hh * NC + BBB * Hh) * (int)sizeof(float); // 163840
        cudaFuncSetAttribute(gru_persistent_kernel,
                             cudaFuncAttributeMaxDynamicSharedMemorySize, smem_bytes);
        dim3 grid(Hh / NC, Bb / BBB);   // (32, 4) = 128 CTAs
        gru_persistent_kernel<<<grid, STEP_THREADS, smem_bytes>>>(
            gi_ptr, gf_ptr, W_hh, b_hh, out);
    }
}

// round 7
// speedup vs baseline: 1.9537x; 1.9488x over previous
#include <cuda_runtime.h>
#include <cuda_bf16.h>
#include <cstddef>

// Problem constants
#define Hh   512
#define INPS 2048
#define FS   1536
#define Bb   128
#define Tt   64
#define MROWS (Bb * Tt)          // 8192

// Persistent-recurrence tiling
#define NC   16                  // hidden cols per CTA
#define BBB  32                  // batch rows per CTA
#define NBLK 128                 // total CTAs (32 col-chunks x 4 batch-chunks)
#define STEP_THREADS 256

// Scratch for precomputed projections (device statics: allocation-free)
__device__ float g_gi[(size_t)MROWS * (3 * Hh)];   // [B*T, 1536]
__device__ float g_gf[(size_t)MROWS * (2 * Hh)];   // [B*T, 1024]
__device__ unsigned int g_bar;                      // grid-barrier counter (monotone)

// ---------------------------------------------------------------------------
// TF32 tensor-core GEMM: C[M,N] = A[M,K] * W[N,K]^T + bias[N]
// CTA tile 128x128x32, 8 warps (2x4), warp tile 64x32 = 4x4 m16n8k8 mma tiles.
// A, W staged to smem as tf32 (cvt.rna on the fly). Pad-4 rows (stride 36)
// makes fragment LDS conflict-free (bank = 4*gid + tig).
// ---------------------------------------------------------------------------
#define GSTRIDE 36   // 32 + 4 pad (uint32 words per smem row)

__device__ __forceinline__ unsigned int f2tf32(float x) {
    unsigned int u;
    asm("cvt.rna.tf32.f32 %0, %1;" : "=r"(u) : "f"(x));
    return u;
}

__global__ __launch_bounds__(256, 2)
void tf32_gemm_bias_kernel(const float* __restrict__ A,
                           const float* __restrict__ W,
                           const float* __restrict__ bias,
                           float* __restrict__ C,
                           int M, int N, int K)
{
    __shared__ unsigned int As[128 * GSTRIDE];
    __shared__ unsigned int Ws[128 * GSTRIDE];

    const int tid  = threadIdx.x;
    const int lane = tid & 31;
    const int warp = tid >> 5;          // 0..7
    const int gid  = lane >> 2;         // 0..7
    const int tig  = lane & 3;          // 0..3
    const int wm   = warp >> 2;         // 0..1 -> M offset wm*64
    const int wn   = warp & 3;          // 0..3 -> N offset wn*32

    const int bm = blockIdx.y;          // M/128
    const int bn = blockIdx.x;          // N/128

    const float* Ablk = A + (size_t)bm * 128 * K;
    const float* Wblk = W + (size_t)bn * 128 * K;

    float acc[4][4][4];                 // [m-tile][n-tile][frag]
#pragma unroll
    for (int i = 0; i < 4; i++)
#pragma unroll
        for (int j = 0; j < 4; j++)
#pragma unroll
            for (int f = 0; f < 4; f++) acc[i][j][f] = 0.0f;

    for (int k0 = 0; k0 < K; k0 += 32) {
        // Stage A and W tiles (128 rows x 32 k) as tf32.
        // 1024 float4 per tile / 256 threads = 4 each.
#pragma unroll
        for (int i = 0; i < 4; i++) {
            int idx = tid + i * 256;            // 0..1023
            int row = idx >> 3;                 // /8
            int c4  = idx & 7;
            float4 v = *(const float4*)(Ablk + (size_t)row * K + k0 + c4 * 4);
            unsigned int* dst = &As[row * GSTRIDE + c4 * 4];
            dst[0] = f2tf32(v.x); dst[1] = f2tf32(v.y);
            dst[2] = f2tf32(v.z); dst[3] = f2tf32(v.w);
        }
#pragma unroll
        for (int i = 0; i < 4; i++) {
            int idx = tid + i * 256;
            int row = idx >> 3;
            int c4  = idx & 7;
            float4 v = *(const float4*)(Wblk + (size_t)row * K + k0 + c4 * 4);
            unsigned int* dst = &Ws[row * GSTRIDE + c4 * 4];
            dst[0] = f2tf32(v.x); dst[1] = f2tf32(v.y);
            dst[2] = f2tf32(v.z); dst[3] = f2tf32(v.w);
        }
        __syncthreads();

#pragma unroll
        for (int kk = 0; kk < 32; kk += 8) {
            // A fragments: 4 m-tiles x 4 regs
            unsigned int af[4][4];
#pragma unroll
            for (int mt = 0; mt < 4; mt++) {
                int r0 = wm * 64 + mt * 16 + gid;
                const unsigned int* p = &As[r0 * GSTRIDE + kk + tig];
                af[mt][0] = p[0];                       // (gid,     tig)
                af[mt][1] = p[8 * GSTRIDE];             // (gid+8,   tig)
                af[mt][2] = p[4];                       // (gid,     tig+4)
                af[mt][3] = p[8 * GSTRIDE + 4];         // (gid+8,   tig+4)
            }
            // B fragments: 4 n-tiles x 2 regs
            unsigned int bf[4][2];
#pragma unroll
            for (int nt = 0; nt < 4; nt++) {
                int n0 = wn * 32 + nt * 8 + gid;
                const unsigned int* p = &Ws[n0 * GSTRIDE + kk + tig];
                bf[nt][0] = p[0];                       // (k=tig,   n=gid)
                bf[nt][1] = p[4];                       // (k=tig+4, n=gid)
            }
#pragma unroll
            for (int mt = 0; mt < 4; mt++)
#pragma unroll
                for (int nt = 0; nt < 4; nt++) {
                    asm volatile(
                        "mma.sync.aligned.m16n8k8.row.col.f32.tf32.tf32.f32 "
                        "{%0,%1,%2,%3}, {%4,%5,%6,%7}, {%8,%9}, {%0,%1,%2,%3};\n"
                        : "+f"(acc[mt][nt][0]), "+f"(acc[mt][nt][1]),
                          "+f"(acc[mt][nt][2]), "+f"(acc[mt][nt][3])
                        : "r"(af[mt][0]), "r"(af[mt][1]),
                          "r"(af[mt][2]), "r"(af[mt][3]),
                          "r"(bf[nt][0]), "r"(bf[nt][1]));
                }
        }
        __syncthreads();
    }

    // Epilogue: bias + store (each thread owns 2 consecutive cols per frag pair)
#pragma unroll
    for (int mt = 0; mt < 4; mt++) {
        const int row = bm * 128 + wm * 64 + mt * 16 + gid;
#pragma unroll
        for (int nt = 0; nt < 4; nt++) {
            const int col = bn * 128 + wn * 32 + nt * 8 + tig * 2;
            const float b0 = bias[col], b1 = bias[col + 1];
            float2 v0 = make_float2(acc[mt][nt][0] + b0, acc[mt][nt][1] + b1);
            float2 v1 = make_float2(acc[mt][nt][2] + b0, acc[mt][nt][3] + b1);
            *(float2*)(C + (size_t)row * N + col)       = v0;
            *(float2*)(C + (size_t)(row + 8) * N + col) = v1;
        }
    }
}

// ---------------------------------------------------------------------------
// Persistent GRU recurrence: ONE kernel runs all 64 timesteps.
// 128 CTAs (32 col-chunks x 4 batch-chunks), all co-resident (1/SM at 160KB smem).
// W_hh slice lives in smem for the whole kernel. Software grid barrier per step.
// ---------------------------------------------------------------------------
__global__ __launch_bounds__(STEP_THREADS, 1)
void gru_persistent_kernel(const float* __restrict__ gi,     // [B*T, 1536]
                           const float* __restrict__ gf,     // [B*T, 1024]
                           const float* __restrict__ W_hh,   // [1536, 512]
                           const float* __restrict__ b_hh,   // [1536]
                           float* __restrict__ out)          // eo [B,T,H] then hT [B,H]
{
    extern __shared__ float sm[];
    float* W_sm = sm;                        // [3][512][NC]  (k-major rows of NC cols)
    float* h_sm = sm + 3 * Hh * NC;          // [BBB][512]

    const int tid = threadIdx.x;
    const int c   = tid & (NC - 1);          // 0..15
    const int bg  = tid >> 4;                // 0..15
    const int colBase = blockIdx.x * NC;     // 0..496
    const int bBase   = blockIdx.y * BBB;    // 0..96
    const int n = colBase + c;

    // ---- One-time: stage W_hh slice (3 gates x NC cols x 512 k) into smem ----
    for (int i = tid; i < 3 * NC * (Hh / 4); i += STEP_THREADS) {
        int r  = i >> 7;          // row 0..(3*NC-1): g*NC + cc
        int kq = i & 127;         // float4 index over k
        int g  = r / NC;
        int cc = r - g * NC;
        float4 v = *(const float4*)(W_hh + (size_t)(g * Hh + colBase + cc) * Hh + kq * 4);
        int k = kq * 4;
        W_sm[((g * Hh) + k + 0) * NC + cc] = v.x;
        W_sm[((g * Hh) + k + 1) * NC + cc] = v.y;
        W_sm[((g * Hh) + k + 2) * NC + cc] = v.z;
        W_sm[((g * Hh) + k + 3) * NC + cc] = v.w;
    }

    const float bhr = b_hh[n];
    const float bhi = b_hh[Hh + n];
    const float bhn = b_hh[2 * Hh + n];

    for (int t = 0; t < Tt; t++) {
        // ---- Stage h_{t-1}[bBase..bBase+31, :] into smem ----
        if (t == 0) {
            float4 z = make_float4(0.f, 0.f, 0.f, 0.f);
            for (int i = tid; i < BBB * (Hh / 4); i += STEP_THREADS)
                *(float4*)(h_sm + i * 4) = z;
        } else {
            for (int i = tid; i < BBB * (Hh / 4); i += STEP_THREADS) {
                int bl = i >> 7;           // local batch
                int kq = i & 127;
                float4 v = *(const float4*)(out +
                    ((size_t)(bBase + bl) * Tt + (t - 1)) * Hh + kq * 4);
                *(float4*)(h_sm + bl * Hh + kq * 4) = v;
            }
        }
        __syncthreads();

        // ---- gh = h_{t-1} @ W_hh^T for this (batch,col) tile ----
        float a00 = 0.f, a01 = 0.f;
        float a10 = 0.f, a11 = 0.f;
        float a20 = 0.f, a21 = 0.f;
        const float* h0p = h_sm + (bg * 2 + 0) * Hh;
        const float* h1p = h_sm + (bg * 2 + 1) * Hh;
        const float* w0p = W_sm + (0 * Hh) * NC + c;
        const float* w1p = W_sm + (1 * Hh) * NC + c;
        const float* w2p = W_sm + (2 * Hh) * NC + c;
#pragma unroll 8
        for (int k = 0; k < Hh; k++) {
            float h0 = h0p[k];
            float h1 = h1p[k];
            float w0 = w0p[k * NC];
            float w1 = w1p[k * NC];
            float w2 = w2p[k * NC];
            a00 = fmaf(w0, h0, a00);  a01 = fmaf(w0, h1, a01);
            a10 = fmaf(w1, h0, a10);  a11 = fmaf(w1, h1, a11);
            a20 = fmaf(w2, h0, a20);  a21 = fmaf(w2, h1, a21);
        }

        // ---- Gates + state update ----
#pragma unroll
        for (int j = 0; j < 2; j++) {
            const int b = bBase + bg * 2 + j;
            const size_t gib = ((size_t)b * Tt + t) * (3 * Hh);
            const size_t gfb = ((size_t)b * Tt + t) * (2 * Hh);

            float ghr = (j ? a01 : a00) + bhr;
            float ghi = (j ? a11 : a10) + bhi;
            float ghn = (j ? a21 : a20) + bhn;

            float xr = gi[gib + n]          + ghr + gf[gfb + n];
            float xi = gi[gib + Hh + n]     + ghi + gf[gfb + Hh + n];
            float resetgate = 1.0f / (1.0f + expf(-xr));
            float inputgate = 1.0f / (1.0f + expf(-xi));
            float newgate   = tanhf(gi[gib + 2 * Hh + n] + resetgate * ghn);

            float hprev = h_sm[(bg * 2 + j) * Hh + n];
            float hy = newgate + inputgate * (hprev - newgate);

            out[((size_t)b * Tt + t) * Hh + n] = hy;
            if (t == Tt - 1)
                out[(size_t)Bb * Tt * Hh + (size_t)b * Hh + n] = hy;
        }

        // ---- Grid-wide barrier (all 128 CTAs co-resident) ----
        __threadfence();
        __syncthreads();
        if (tid == 0) {
            unsigned int old  = atomicAdd(&g_bar, 1u);
            unsigned int need = (old / NBLK + 1u) * NBLK;
            while (true) {
                unsigned int cur;
                asm volatile("ld.acquire.gpu.u32 %0, [%1];"
                             : "=r"(cur) : "l"(&g_bar));
                if (cur >= need) break;
            }
            __threadfence();
        }
        __syncthreads();
    }
}

// ---------------------------------------------------------------------------
// Launch
// ---------------------------------------------------------------------------
extern "C" void kernel_launch(void* const* d_in, const int* in_sizes, int n_in,
                              void* d_out, int out_size)
{
    const float* feat0 = (const float*)d_in[0];   // [B,T,FS]
    const float* feat1 = (const float*)d_in[1];   // [B,T,IN]
    const float* W_ih  = (const float*)d_in[2];   // [3H, IN]
    const float* b_ih  = (const float*)d_in[3];   // [3H]
    const float* W_hh  = (const float*)d_in[4];   // [3H, H]
    const float* b_hh  = (const float*)d_in[5];   // [3H]
    const float* W_fh  = (const float*)d_in[6];   // [2H, FS]
    const float* b_fh  = (const float*)d_in[7];   // [2H]
    float* out = (float*)d_out;

    float *gi_ptr, *gf_ptr;
    cudaGetSymbolAddress((void**)&gi_ptr, g_gi);
    cudaGetSymbolAddress((void**)&gf_ptr, g_gf);

    // gi = feat1 @ W_ih^T + b_ih : M=8192, N=1536, K=2048  (tf32 tensor path)
    {
        dim3 grid((3 * Hh) / 128, MROWS / 128);   // (12, 64)
        tf32_gemm_bias_kernel<<<grid, 256>>>(feat1, W_ih, b_ih, gi_ptr,
                                             MROWS, 3 * Hh, INPS);
    }
    // gf = feat0 @ W_fh^T + b_fh : M=8192, N=1024, K=1536  (tf32 tensor path)
    {
        dim3 grid((2 * Hh) / 128, MROWS / 128);   // (8, 64)
        tf32_gemm_bias_kernel<<<grid, 256>>>(feat0, W_fh, b_fh, gf_ptr,
                                             MROWS, 2 * Hh, FS);
    }
    // Recurrence: single persistent kernel, 64 steps internally
    {
        const int smem_bytes = (3 * Hh * NC + BBB * Hh) * (int)sizeof(float); // 163840
        cudaFuncSetAttribute(gru_persistent_kernel,
                             cudaFuncAttributeMaxDynamicSharedMemorySize, smem_bytes);
        dim3 grid(Hh / NC, Bb / BBB);   // (32, 4) = 128 CTAs
        gru_persistent_kernel<<<grid, STEP_THREADS, smem_bytes>>>(
            gi_ptr, gf_ptr, W_hh, b_hh, out);
    }
}